// round 16
// baseline (speedup 1.0000x reference)
#include <cuda_runtime.h>
#include <cuda_bf16.h>
#include <cuda_fp16.h>
#include <math.h>
#include <stdint.h>

// ---------------------------------------------------------------------------
// ChannelBlock: B=32, N=784 (28x28), C=384, heads=8, hd=48, MLP hidden=1536
// bf16 mma.sync GEMMs (R8 config, pipe ceiling), 4x7-tiled cpe_ln,
// fp16 k/v path for attnA (halved load bytes), fused softmax+attnB.
// ---------------------------------------------------------------------------

#define Bsz   32
#define Ntok  784
#define Cdim  384
#define NT    (Bsz * Ntok)     // 25088
#define H3    (3 * Cdim)       // 1152
#define HID   1536
#define NH    8
#define HD    48
#define NCHUNK 7               // attnA token chunks (112 each)
#define KVROW (H3 - Cdim)      // 768 halfs per token in kv buffer

typedef __nv_bfloat16 bf16;

// scratch (static device memory; no allocation anywhere)
__device__ float g_xa  [(size_t)NT * Cdim];
__device__ bf16  g_ln  [(size_t)NT * Cdim];
__device__ float g_qkv [(size_t)NT * H3];     // only q columns written/read
__device__ __half g_kvh[(size_t)NT * KVROW];  // fp16 k|v
__device__ float g_attn[(size_t)NCHUNK * Bsz * NH * HD * HD];  // partial logits
__device__ bf16  g_att [(size_t)NT * Cdim];
__device__ float g_xb  [(size_t)NT * Cdim];
__device__ bf16  g_h   [(size_t)NT * HID];
// bf16 weights: qkv | proj | fc1 | fc2
#define W_QKV 0
#define W_PROJ (H3 * Cdim)
#define W_FC1  (W_PROJ + Cdim * Cdim)
#define W_FC2  (W_FC1 + HID * Cdim)
#define W_TOT  (W_FC2 + Cdim * HID)
__device__ bf16  g_wbf [(size_t)W_TOT];

// single launch: convert all 4 weight matrices to bf16
__global__ void cvt_all_kernel(const float* __restrict__ qkv_w,
                               const float* __restrict__ proj_w,
                               const float* __restrict__ fc1_w,
                               const float* __restrict__ fc2_w,
                               bf16* __restrict__ out)
{
    int i = blockIdx.x * blockDim.x + threadIdx.x;
    if (i >= W_TOT) return;
    float v;
    if (i < W_PROJ)      v = qkv_w[i];
    else if (i < W_FC1)  v = proj_w[i - W_PROJ];
    else if (i < W_FC2)  v = fc1_w[i - W_FC1];
    else                 v = fc2_w[i - W_FC2];
    out[i] = __float2bfloat16(v);
}

// ---------------------------------------------------------------------------
// Tiled fused cpe + LN: 4 rows x 7 cols of tokens per block (R14).
// ---------------------------------------------------------------------------
#define TJC 7
#define TIR 4
#define NTOK_B (TIR * TJC)                 // 28 tokens per block
#define SLOTS ((TIR + 2) * (TJC + 2))      // 54 halo slots
#define CPE_SMEM ((SLOTS * Cdim + 2 * 12 * NTOK_B + 2 * NTOK_B) * 4)

__global__ __launch_bounds__(Cdim)
void cpe_ln_kernel(const float* __restrict__ x,
                   const float* __restrict__ w,
                   const float* __restrict__ bias,
                   const float* __restrict__ lng,
                   const float* __restrict__ lnb,
                   float* __restrict__ y,
                   bf16* __restrict__ yln)
{
    extern __shared__ float dsm[];
    float (*tile)[TJC + 2][Cdim] = (float (*)[TJC + 2][Cdim])dsm;
    float* redS  = dsm + SLOTS * Cdim;
    float* redQ  = redS + 12 * NTOK_B;
    float* stats = redQ + 12 * NTOK_B;     // [NTOK_B][2]

    int c  = threadIdx.x;
    int jg = blockIdx.x;                   // 0..3
    int ig = blockIdx.y;                   // 0..6
    int b  = blockIdx.z;
    int j0 = jg * TJC, i0 = ig * TIR;

    const float* xb = x + (size_t)b * Ntok * Cdim;

#pragma unroll
    for (int s = 0; s < SLOTS; s++) {
        int ri = s / (TJC + 2) + i0 - 1;
        int cj = s % (TJC + 2) + j0 - 1;
        float v = 0.f;
        if (ri >= 0 && ri < 28 && cj >= 0 && cj < 28)
            v = xb[(size_t)(ri * 28 + cj) * Cdim + c];
        tile[s / (TJC + 2)][s % (TJC + 2)][c] = v;
    }
    __syncthreads();

    const float* wc = w + c * 9;
    float wr[9];
#pragma unroll
    for (int q = 0; q < 9; q++) wr[q] = wc[q];
    float bs = bias[c];

    float val[NTOK_B];
#pragma unroll
    for (int r = 0; r < TIR; r++) {
#pragma unroll
        for (int jt = 0; jt < TJC; jt++) {
            float acc = bs;
#pragma unroll
            for (int di = 0; di < 3; di++)
#pragma unroll
                for (int dj = 0; dj < 3; dj++)
                    acc += wr[di * 3 + dj] * tile[r + di][jt + dj][c];
            val[r * TJC + jt] = tile[r + 1][jt + 1][c] + acc;
        }
    }

    int warp = c >> 5, lane = c & 31;
#pragma unroll
    for (int q = 0; q < NTOK_B; q++) {
        float s = val[q], sq = val[q] * val[q];
#pragma unroll
        for (int o = 16; o; o >>= 1) {
            s  += __shfl_xor_sync(0xffffffffu, s,  o);
            sq += __shfl_xor_sync(0xffffffffu, sq, o);
        }
        if (lane == 0) { redS[warp * NTOK_B + q] = s; redQ[warp * NTOK_B + q] = sq; }
    }
    __syncthreads();
    if (c < NTOK_B) {
        float ts = 0.f, tq = 0.f;
#pragma unroll
        for (int k = 0; k < 12; k++) { ts += redS[k * NTOK_B + c]; tq += redQ[k * NTOK_B + c]; }
        float mean = ts * (1.f / Cdim);
        float var  = tq * (1.f / Cdim) - mean * mean;
        stats[c * 2]     = mean;
        stats[c * 2 + 1] = rsqrtf(var + 1e-5f);
    }
    __syncthreads();

    float gg = lng[c], bb = lnb[c];
#pragma unroll
    for (int r = 0; r < TIR; r++) {
#pragma unroll
        for (int jt = 0; jt < TJC; jt++) {
            int q = r * TJC + jt;
            size_t idx = ((size_t)b * Ntok + (i0 + r) * 28 + j0 + jt) * Cdim + c;
            float v = val[q];
            y[idx] = v;
            yln[idx] = __float2bfloat16((v - stats[q * 2]) * stats[q * 2 + 1] * gg + bb);
        }
    }
}

// ---------------------------------------------------------------------------
// bf16 GEMM (R8 config). EPI: 0 none(fp32); 2 bias+GELU->bf16; 3 bias+res;
// 4 = qkv split: q tiles (col0<Cdim) -> fp32 Cout; k/v tiles -> fp16 via res ptr.
// ---------------------------------------------------------------------------
#define BM 128
#define BN 128
#define BK 32
#define STAGES 3
#define ASTG (BM * 64)
#define STG_BYTES (2 * ASTG)

__device__ __forceinline__ void cp16(unsigned saddr, const void* g)
{
    asm volatile("cp.async.cg.shared.global [%0], [%1], 16;\n" :: "r"(saddr), "l"(g));
}
__device__ __forceinline__ void ldsm4(uint32_t& r0, uint32_t& r1, uint32_t& r2,
                                      uint32_t& r3, uint32_t a)
{
    asm volatile("ldmatrix.sync.aligned.m8n8.x4.shared.b16 {%0,%1,%2,%3}, [%4];"
                 : "=r"(r0), "=r"(r1), "=r"(r2), "=r"(r3) : "r"(a));
}

template<int EPI, int K>
__global__ __launch_bounds__(256, 2)
void gemm_bf16(const bf16* __restrict__ A, const bf16* __restrict__ W,
               const float* __restrict__ bias, const float* __restrict__ res,
               void* __restrict__ Cout, int M, int N)
{
    __shared__ alignas(128) char sm[STAGES * STG_BYTES];
    uint32_t sb = (uint32_t)__cvta_generic_to_shared(sm);

    int tid = threadIdx.x;
    int w = tid >> 5, l = tid & 31;
    int row0 = blockIdx.y * BM;
    int col0 = blockIdx.x * BN;
    int wm = (w & 1) * 64;
    int wn = (w >> 1) * 32;
    int g = l >> 2, t = l & 3;

    int jj  = l >> 3;
    int rlo = l & 7;
    int rowA_in = (jj & 1) * 8 + rlo;
    int cA = jj >> 1;
    uint32_t aoff[4], axr[4];
#pragma unroll
    for (int mi = 0; mi < 4; mi++) {
        int rA = wm + mi * 16 + rowA_in;
        aoff[mi] = (uint32_t)rA * 64;
        axr[mi]  = (uint32_t)(((rA >> 1) & 3) << 4);
    }
    int rowB_in = (jj >> 1) * 8 + rlo;
    int cB = jj & 1;
    uint32_t boff[2], bxr[2];
#pragma unroll
    for (int p = 0; p < 2; p++) {
        int rB = wn + p * 16 + rowB_in;
        boff[p] = (uint32_t)(ASTG + rB * 64);
        bxr[p]  = (uint32_t)(((rB >> 1) & 3) << 4);
    }

    float acc[4][4][4];
#pragma unroll
    for (int mi = 0; mi < 4; mi++)
#pragma unroll
        for (int ni = 0; ni < 4; ni++)
#pragma unroll
            for (int r = 0; r < 4; r++) acc[mi][ni][r] = 0.f;

    constexpr int NS = K / BK;

    auto load_stage = [&](int s) {
        uint32_t tb = sb + (s % STAGES) * STG_BYTES;
        int kt = s * BK;
        const bf16* Ab = A + (size_t)row0 * K + kt;
        const bf16* Wb = W + (size_t)col0 * K + kt;
#pragma unroll
        for (int i = 0; i < 2; i++) {
            int id = tid + i * 256;
            int r = id >> 2, c = id & 3;
            int cs = c ^ ((r >> 1) & 3);
            cp16(tb + r * 64 + cs * 16, Ab + (size_t)r * K + c * 8);
            cp16(tb + ASTG + r * 64 + cs * 16, Wb + (size_t)r * K + c * 8);
        }
    };

    load_stage(0);
    asm volatile("cp.async.commit_group;\n");
    load_stage(1);
    asm volatile("cp.async.commit_group;\n");

#pragma unroll
    for (int s = 0; s < NS; s++) {
        asm volatile("cp.async.wait_group 1;\n");
        __syncthreads();

        if (s + STAGES - 1 < NS) load_stage(s + STAGES - 1);
        asm volatile("cp.async.commit_group;\n");

        uint32_t stb = sb + (s % STAGES) * STG_BYTES;
#pragma unroll
        for (int kk = 0; kk < 2; kk++) {
            uint32_t c0 = kk * 2;
            uint32_t af[4][4], bq[2][4];
#pragma unroll
            for (int mi = 0; mi < 4; mi++)
                ldsm4(af[mi][0], af[mi][1], af[mi][2], af[mi][3],
                      stb + aoff[mi] + ((((c0 + cA) << 4)) ^ axr[mi]));
#pragma unroll
            for (int p = 0; p < 2; p++)
                ldsm4(bq[p][0], bq[p][1], bq[p][2], bq[p][3],
                      stb + boff[p] + ((((c0 + cB) << 4)) ^ bxr[p]));

#pragma unroll
            for (int mi = 0; mi < 4; mi++)
#pragma unroll
                for (int ni = 0; ni < 4; ni++) {
                    int p = ni >> 1, q = ni & 1;
                    asm volatile(
                        "mma.sync.aligned.m16n8k16.row.col.f32.bf16.bf16.f32 "
                        "{%0,%1,%2,%3}, {%4,%5,%6,%7}, {%8,%9}, {%0,%1,%2,%3};"
                        : "+f"(acc[mi][ni][0]), "+f"(acc[mi][ni][1]),
                          "+f"(acc[mi][ni][2]), "+f"(acc[mi][ni][3])
                        : "r"(af[mi][0]), "r"(af[mi][1]), "r"(af[mi][2]), "r"(af[mi][3]),
                          "r"(bq[p][2 * q]), "r"(bq[p][2 * q + 1]));
                }
        }
    }

#pragma unroll
    for (int mi = 0; mi < 4; mi++) {
#pragma unroll
        for (int ni = 0; ni < 4; ni++) {
            int col = col0 + wn + ni * 8 + 2 * t;
#pragma unroll
            for (int half2i = 0; half2i < 2; half2i++) {
                int row = row0 + wm + mi * 16 + g + half2i * 8;
                size_t idx = (size_t)row * N + col;
                float v0 = acc[mi][ni][2 * half2i];
                float v1 = acc[mi][ni][2 * half2i + 1];
                if (EPI == 0) {
                    *(float2*)&((float*)Cout)[idx] = make_float2(v0, v1);
                } else if (EPI == 2) {
                    float2 bv = *(const float2*)&bias[col];
                    v0 += bv.x; v1 += bv.y;
                    v0 = 0.5f * v0 * (1.f + erff(v0 * 0.7071067811865475f));
                    v1 = 0.5f * v1 * (1.f + erff(v1 * 0.7071067811865475f));
                    __nv_bfloat162 pk;
                    pk.x = __float2bfloat16(v0);
                    pk.y = __float2bfloat16(v1);
                    *(__nv_bfloat162*)&((bf16*)Cout)[idx] = pk;
                } else if (EPI == 3) {
                    float2 bv = *(const float2*)&bias[col];
                    float2 rv = *(const float2*)&res[idx];
                    v0 += bv.x + rv.x; v1 += bv.y + rv.y;
                    *(float2*)&((float*)Cout)[idx] = make_float2(v0, v1);
                } else if (EPI == 4) {
                    if (col0 < Cdim) {
                        *(float2*)&((float*)Cout)[idx] = make_float2(v0, v1);
                    } else {
                        __half* kvp = (__half*)const_cast<float*>(res);
                        size_t kidx = (size_t)row * KVROW + (col - Cdim);
                        *(__half2*)&kvp[kidx] = __floats2half2_rn(v0, v1);
                    }
                }
            }
        }
    }
}

// ---------------------------------------------------------------------------
// Channel attention stage A: per (bh, chunk) partial (k*s)^T v over 112 tokens.
// k/v read as fp16 (uint4 = 8 halfs), converted to fp32 in the staging store;
// smem layout, fragment loads, and per-output fmaf order unchanged.
// ---------------------------------------------------------------------------
#define ATHR 144
#define KVS  56    // padded row stride (floats), 16B aligned
__global__ __launch_bounds__(ATHR, 7)
void attnA_partial(const __half* __restrict__ kvh, float* __restrict__ partial)
{
    __shared__ float ks[2][16][KVS];
    __shared__ float vs[2][16][KVS];

    int bh = blockIdx.x;
    int b = bh >> 3, h = bh & 7;
    int chunk = blockIdx.y;
    int nstart = chunk * 112;
    int tid = threadIdx.x;
    int tx = tid % 12, ty = tid / 12;
    const float scale = 0.14433756729740643f;   // 48^-0.5

    const __half* base = kvh + (size_t)b * Ntok * KVROW + h * HD;

    // 192 uint4 slots per tile (2 matrices x 16 tokens x 6 chunks of 8 halfs)
    int idx0 = tid;                             // always valid (<192)
    int buf0 = idx0 / 96, rem0 = idx0 % 96;
    int nn0 = rem0 / 6, d80 = rem0 - nn0 * 6;
    bool has1 = (tid < 48);
    int idx1 = tid + 144;
    int buf1 = idx1 / 96, rem1 = idx1 % 96;
    int nn1 = rem1 / 6, d81 = rem1 - nn1 * 6;

    uint4 pf0, pf1;
    auto prefetch = [&](int n0) {
        pf0 = *(const uint4*)(base + (size_t)(n0 + nn0) * KVROW + buf0 * (KVROW / 2) + d80 * 8);
        if (has1)
            pf1 = *(const uint4*)(base + (size_t)(n0 + nn1) * KVROW + buf1 * (KVROW / 2) + d81 * 8);
    };
    auto cvst = [&](uint4 pf, int buf, int nn, int d8, int sb2) {
        __half2* hp = (__half2*)&pf;
        float2 f0 = __half22float2(hp[0]);
        float2 f1 = __half22float2(hp[1]);
        float2 f2 = __half22float2(hp[2]);
        float2 f3 = __half22float2(hp[3]);
        if (buf == 0) {
            f0.x *= scale; f0.y *= scale; f1.x *= scale; f1.y *= scale;
            f2.x *= scale; f2.y *= scale; f3.x *= scale; f3.y *= scale;
            *(float4*)&ks[sb2][nn][d8 * 8]     = make_float4(f0.x, f0.y, f1.x, f1.y);
            *(float4*)&ks[sb2][nn][d8 * 8 + 4] = make_float4(f2.x, f2.y, f3.x, f3.y);
        } else {
            *(float4*)&vs[sb2][nn][d8 * 8]     = make_float4(f0.x, f0.y, f1.x, f1.y);
            *(float4*)&vs[sb2][nn][d8 * 8 + 4] = make_float4(f2.x, f2.y, f3.x, f3.y);
        }
    };
    auto store_pf = [&](int sb2) {
        cvst(pf0, buf0, nn0, d80, sb2);
        if (has1) cvst(pf1, buf1, nn1, d81, sb2);
    };

    float acc[4][4];
#pragma unroll
    for (int i = 0; i < 4; i++)
#pragma unroll
        for (int j = 0; j < 4; j++) acc[i][j] = 0.f;

    prefetch(nstart);
    store_pf(0);
    __syncthreads();

#pragma unroll
    for (int t = 0; t < 7; t++) {
        if (t < 6) prefetch(nstart + (t + 1) * 16);
        int cb = t & 1;
#pragma unroll
        for (int nn = 0; nn < 16; nn++) {
            float4 rk = *(const float4*)&ks[cb][nn][ty * 4];
            float4 rv = *(const float4*)&vs[cb][nn][tx * 4];
            float k[4] = {rk.x, rk.y, rk.z, rk.w};
            float v[4] = {rv.x, rv.y, rv.z, rv.w};
#pragma unroll
            for (int i = 0; i < 4; i++)
#pragma unroll
                for (int j = 0; j < 4; j++)
                    acc[i][j] = fmaf(k[i], v[j], acc[i][j]);
        }
        if (t < 6) store_pf((t + 1) & 1);
        __syncthreads();
    }

    float* o = partial + ((size_t)chunk * (Bsz * NH) + bh) * (HD * HD);
#pragma unroll
    for (int i = 0; i < 4; i++) {
        float4 st = make_float4(acc[i][0], acc[i][1], acc[i][2], acc[i][3]);
        *(float4*)&o[(ty * 4 + i) * HD + tx * 4] = st;
    }
}

// ---------------------------------------------------------------------------
// Fused softmax + attnB, 2-way N split; float4 partial-sum loads (R15).
// ---------------------------------------------------------------------------
__global__ __launch_bounds__(384)
void attnBF_kernel(const float* __restrict__ qkv, const float* __restrict__ partial,
                   bf16* __restrict__ out)
{
    __shared__ float at[HD * HD];
    __shared__ float qs[56][HD];

    int bh = blockIdx.x;
    int half = blockIdx.y;
    int b = bh >> 3, h = bh & 7;
    int tid = threadIdx.x;

#pragma unroll
    for (int it = 0; it < 2; it++) {
        int idx4 = tid + it * 384;
        if (idx4 < 576) {
            float4 s = make_float4(0.f, 0.f, 0.f, 0.f);
#pragma unroll
            for (int ch = 0; ch < NCHUNK; ch++) {
                const float4 p = *(const float4*)&partial[
                    ((size_t)ch * (Bsz * NH) + bh) * (HD * HD) + idx4 * 4];
                s.x += p.x; s.y += p.y; s.z += p.z; s.w += p.w;
            }
            *(float4*)&at[idx4 * 4] = s;
        }
    }
    __syncthreads();

    if (tid < HD) {
        float* row = &at[tid * HD];
        float m = -1e30f;
#pragma unroll
        for (int e = 0; e < HD; e++) m = fmaxf(m, row[e]);
        float s = 0.f;
#pragma unroll
        for (int e = 0; e < HD; e++) { float tv = expf(row[e] - m); row[e] = tv; s += tv; }
        float inv = 1.f / s;
#pragma unroll
        for (int e = 0; e < HD; e++) row[e] *= inv;
    }
    __syncthreads();

    int nl = tid / HD;
    int d  = tid - nl * HD;
    float4 arow[12];
#pragma unroll
    for (int e4 = 0; e4 < 12; e4++)
        arow[e4] = *(float4*)&at[d * HD + e4 * 4];

    const float* qb = qkv + (size_t)b * Ntok * H3 + h * HD + d;
    bf16* ob = out + (size_t)b * Ntok * Cdim + h * HD + d;

    int nbeg = half * 392;
    for (int n0 = nbeg; n0 < nbeg + 392; n0 += 56) {
#pragma unroll
        for (int r = 0; r < 7; r++)
            qs[nl + 8 * r][d] = qb[(size_t)(n0 + nl + 8 * r) * H3];
        __syncthreads();

        float acc[7] = {0.f, 0.f, 0.f, 0.f, 0.f, 0.f, 0.f};
#pragma unroll
        for (int e4 = 0; e4 < 12; e4++) {
            float4 ar = arow[e4];
#pragma unroll
            for (int r = 0; r < 7; r++) {
                float4 qv = *(float4*)&qs[nl + 8 * r][e4 * 4];
                acc[r] = fmaf(ar.x, qv.x, acc[r]);
                acc[r] = fmaf(ar.y, qv.y, acc[r]);
                acc[r] = fmaf(ar.z, qv.z, acc[r]);
                acc[r] = fmaf(ar.w, qv.w, acc[r]);
            }
        }
#pragma unroll
        for (int r = 0; r < 7; r++)
            ob[(size_t)(n0 + nl + 8 * r) * Cdim] = __float2bfloat16(acc[r]);
        __syncthreads();
    }
}

// ---------------------------------------------------------------------------
// Launch
// ---------------------------------------------------------------------------
extern "C" void kernel_launch(void* const* d_in, const int* in_sizes, int n_in,
                              void* d_out, int out_size)
{
    const float* x       = (const float*)d_in[0];
    const float* cpe0_w  = (const float*)d_in[3];
    const float* cpe0_b  = (const float*)d_in[4];
    const float* cpe1_w  = (const float*)d_in[5];
    const float* cpe1_b  = (const float*)d_in[6];
    const float* norm1_g = (const float*)d_in[7];
    const float* norm1_b = (const float*)d_in[8];
    const float* qkv_w   = (const float*)d_in[9];
    const float* proj_w  = (const float*)d_in[10];
    const float* proj_b  = (const float*)d_in[11];
    const float* norm2_g = (const float*)d_in[12];
    const float* norm2_b = (const float*)d_in[13];
    const float* fc1_w   = (const float*)d_in[14];
    const float* fc1_b   = (const float*)d_in[15];
    const float* fc2_w   = (const float*)d_in[16];
    const float* fc2_b   = (const float*)d_in[17];
    float* out = (float*)d_out;

    float *xa, *qkvb, *attn, *xb;
    __half *kvh;
    bf16 *ln, *att, *hbuf, *wbf;
    cudaGetSymbolAddress((void**)&xa,    g_xa);
    cudaGetSymbolAddress((void**)&ln,    g_ln);
    cudaGetSymbolAddress((void**)&qkvb,  g_qkv);
    cudaGetSymbolAddress((void**)&kvh,   g_kvh);
    cudaGetSymbolAddress((void**)&attn,  g_attn);
    cudaGetSymbolAddress((void**)&att,   g_att);
    cudaGetSymbolAddress((void**)&xb,    g_xb);
    cudaGetSymbolAddress((void**)&hbuf,  g_h);
    cudaGetSymbolAddress((void**)&wbf,   g_wbf);

    cudaFuncSetAttribute(cpe_ln_kernel, cudaFuncAttributeMaxDynamicSharedMemorySize, CPE_SMEM);

    dim3 cpeGrid(4, TJC, Bsz);

    // one launch: convert all weights to bf16
    cvt_all_kernel<<<(W_TOT + 255) / 256, 256>>>(qkv_w, proj_w, fc1_w, fc2_w, wbf);

    // xa = cpe0(x); ln = LN1(xa) [bf16]
    cpe_ln_kernel<<<cpeGrid, Cdim, CPE_SMEM>>>(x, cpe0_w, cpe0_b, norm1_g, norm1_b, xa, ln);
    // qkv: q tiles -> fp32 qkvb, k/v tiles -> fp16 kvh (EPI=4, kvh passed as res)
    gemm_bf16<4, Cdim><<<dim3(H3 / BN, NT / BM), 256>>>(ln, wbf + W_QKV, nullptr,
                                                        (const float*)kvh, qkvb, NT, H3);
    // channel attention
    attnA_partial<<<dim3(Bsz * NH, NCHUNK), ATHR>>>(kvh, attn);
    attnBF_kernel<<<dim3(Bsz * NH, 2), 384>>>(qkvb, attn, att);
    // xb = xa + att @ proj_w^T + proj_b  (fp32 out)
    gemm_bf16<3, Cdim><<<dim3(Cdim / BN, NT / BM), 256>>>(att, wbf + W_PROJ, proj_b, xa, xb, NT, Cdim);
    // xc = cpe1(xb) -> xa ; ln = LN2(xc) [bf16]
    cpe_ln_kernel<<<cpeGrid, Cdim, CPE_SMEM>>>(xb, cpe1_w, cpe1_b, norm2_g, norm2_b, xa, ln);
    // h = gelu(ln2 @ fc1^T + b1) [bf16 out]
    gemm_bf16<2, Cdim><<<dim3(HID / BN, NT / BM), 256>>>(ln, wbf + W_FC1, fc1_b, nullptr, hbuf, NT, HID);
    // out = xc + h @ fc2^T + b2 (fp32 out)
    gemm_bf16<3, HID><<<dim3(Cdim / BN, NT / BM), 256>>>(hbuf, wbf + W_FC2, fc2_b, xa, out, NT, Cdim);
}